// round 1
// baseline (speedup 1.0000x reference)
#include <cuda_runtime.h>
#include <math.h>

#define BB      4
#define LL      288
#define NNH     170
#define DDIM    128
#define NHEADS  8
#define WSZ     12
#define SHIFTSZ 6
#define HIDD    512
#define NWIN    24
#define MTOK    (BB * LL * NNH)   // 195840

// Scratch (static device globals — allocation-free)
__device__ float g_qkv[(size_t)MTOK * 384];   // (b,n,ls) x [q|k|v] heads-major
__device__ float g_attn[(size_t)MTOK * DDIM]; // (b,n,ls) attention output
__device__ float g_x1[(size_t)MTOK * DDIM];   // (b,n,l)  post-attn residual state
__device__ float g_h[(size_t)MTOK * HIDD];    // (b,n,l)  mlp hidden

// ---------------------------------------------------------------------------
// Tiled SGEMM, 128x128 block tile, BK=8, 256 threads, 8x8 per-thread microtile.
// MODE 0: A = gather(x, shift+transpose), out = qkv + bias          (K=128,N=384)
// MODE 1: A = g_attn, epilogue = unshift + LN1(g1,b1) + residual(x) (K=128,N=128)
// MODE 2: A = g_x1,   epilogue = GELU(.+bias)                       (K=128,N=512)
// MODE 3: A = g_h,    epilogue = LN2(g2,b2) + residual(g_x1),
//                     scatter to (B,L,N,D) output                   (K=512,N=128)
// ---------------------------------------------------------------------------
template<int MODE, int K, int NDIM>
__global__ __launch_bounds__(256)
void gemm_kernel(const float* __restrict__ W, const float* __restrict__ bias,
                 float* __restrict__ outp, const float* __restrict__ xin,
                 const float* __restrict__ gamma, const float* __restrict__ beta)
{
    __shared__ float As[8][128];
    __shared__ float Bs[8][128];

    const int tid = threadIdx.x;
    const int tx  = tid & 15;
    const int ty  = tid >> 4;
    const int rowBlock = blockIdx.x * 128;
    const int colBlock = blockIdx.y * 128;

    // A-tile loader assignment: row = tid/2, one float4 at k-offset (tid&1)*4
    const int la_row = tid >> 1;
    const int la_k   = (tid & 1) * 4;
    const int aRowG  = rowBlock + la_row;

    const float* arow;
    if (MODE == 0) {
        // row index space is (b, n, ls); gather from x (B,L,N,D) at l = ls - SHIFT
        int b   = aRowG / (NNH * LL);
        int rem = aRowG % (NNH * LL);
        int n   = rem / LL;
        int ls  = rem % LL;
        int l   = ls - SHIFTSZ; if (l < 0) l += LL;
        arow = xin + ((size_t)(b * LL + l) * NNH + n) * DDIM;
    } else if (MODE == 1) {
        arow = g_attn + (size_t)aRowG * K;
    } else if (MODE == 2) {
        arow = g_x1 + (size_t)aRowG * K;
    } else {
        arow = g_h + (size_t)aRowG * K;
    }

    // B-tile loader: row = tid/32 (0..7), col = (tid&31)*4
    const int lb_row = tid >> 5;
    const int lb_col = (tid & 31) * 4;

    float acc[8][8];
    #pragma unroll
    for (int i = 0; i < 8; i++)
        #pragma unroll
        for (int j = 0; j < 8; j++) acc[i][j] = 0.f;

    for (int k0 = 0; k0 < K; k0 += 8) {
        float4 av = *(const float4*)(arow + k0 + la_k);
        As[la_k + 0][la_row] = av.x;
        As[la_k + 1][la_row] = av.y;
        As[la_k + 2][la_row] = av.z;
        As[la_k + 3][la_row] = av.w;
        float4 bv = *(const float4*)(W + (size_t)(k0 + lb_row) * NDIM + colBlock + lb_col);
        *(float4*)(&Bs[lb_row][lb_col]) = bv;
        __syncthreads();
        #pragma unroll
        for (int kk = 0; kk < 8; kk++) {
            float ar[8], br[8];
            *(float4*)(ar)     = *(const float4*)(&As[kk][ty * 8]);
            *(float4*)(ar + 4) = *(const float4*)(&As[kk][ty * 8 + 4]);
            *(float4*)(br)     = *(const float4*)(&Bs[kk][tx * 8]);
            *(float4*)(br + 4) = *(const float4*)(&Bs[kk][tx * 8 + 4]);
            #pragma unroll
            for (int i = 0; i < 8; i++)
                #pragma unroll
                for (int j = 0; j < 8; j++)
                    acc[i][j] += ar[i] * br[j];
        }
        __syncthreads();
    }

    // bias
    #pragma unroll
    for (int j = 0; j < 8; j++) {
        float bj = bias[colBlock + tx * 8 + j];
        #pragma unroll
        for (int i = 0; i < 8; i++) acc[i][j] += bj;
    }

    if (MODE == 0) {
        #pragma unroll
        for (int i = 0; i < 8; i++) {
            int r = rowBlock + ty * 8 + i;
            float* dst = g_qkv + (size_t)r * 384 + colBlock + tx * 8;
            *(float4*)(dst)     = make_float4(acc[i][0], acc[i][1], acc[i][2], acc[i][3]);
            *(float4*)(dst + 4) = make_float4(acc[i][4], acc[i][5], acc[i][6], acc[i][7]);
        }
        return;
    }
    if (MODE == 2) {
        #pragma unroll
        for (int i = 0; i < 8; i++) {
            int r = rowBlock + ty * 8 + i;
            float* dst = g_h + (size_t)r * HIDD + colBlock + tx * 8;
            float v[8];
            #pragma unroll
            for (int j = 0; j < 8; j++) { float a = acc[i][j]; v[j] = a * normcdff(a); }
            *(float4*)(dst)     = make_float4(v[0], v[1], v[2], v[3]);
            *(float4*)(dst + 4) = make_float4(v[4], v[5], v[6], v[7]);
        }
        return;
    }

    if (MODE == 1 || MODE == 3) {
        // LayerNorm over the full 128-wide row (one CTA owns the whole row).
        __shared__ float ps [128][17];
        __shared__ float ps2[128][17];
        #pragma unroll
        for (int i = 0; i < 8; i++) {
            float s = 0.f, s2 = 0.f;
            #pragma unroll
            for (int j = 0; j < 8; j++) { s += acc[i][j]; s2 += acc[i][j] * acc[i][j]; }
            ps [ty * 8 + i][tx] = s;
            ps2[ty * 8 + i][tx] = s2;
        }
        __syncthreads();
        #pragma unroll
        for (int i = 0; i < 8; i++) {
            int lr = ty * 8 + i;
            float s = 0.f, s2 = 0.f;
            #pragma unroll
            for (int t = 0; t < 16; t++) { s += ps[lr][t]; s2 += ps2[lr][t]; }
            float mean = s  * (1.f / 128.f);
            float var  = s2 * (1.f / 128.f) - mean * mean;
            var = fmaxf(var, 0.f);
            float rstd = rsqrtf(var + 1e-5f);
            int r = rowBlock + lr;

            if (MODE == 1) {
                // row space (b,n,ls) -> output row (b,n,lo) with lo = ls - SHIFT
                int b   = r / (NNH * LL);
                int rem = r % (NNH * LL);
                int n   = rem / LL;
                int ls  = rem % LL;
                int lo  = ls - SHIFTSZ; if (lo < 0) lo += LL;
                const float* res = xin + ((size_t)(b * LL + lo) * NNH + n) * DDIM + tx * 8;
                float* dst = g_x1 + ((size_t)(b * NNH + n) * LL + lo) * DDIM + tx * 8;
                #pragma unroll
                for (int j = 0; j < 8; j++) {
                    int col = tx * 8 + j;
                    dst[j] = (acc[i][j] - mean) * rstd * gamma[col] + beta[col] + res[j];
                }
            } else {
                // row space (b,n,l); residual = g_x1; scatter to (B,L,N,D)
                int b   = r / (NNH * LL);
                int rem = r % (NNH * LL);
                int n   = rem / LL;
                int l   = rem % LL;
                const float* res = g_x1 + (size_t)r * DDIM + tx * 8;
                float* dst = outp + ((size_t)(b * LL + l) * NNH + n) * DDIM + tx * 8;
                #pragma unroll
                for (int j = 0; j < 8; j++) {
                    int col = tx * 8 + j;
                    dst[j] = (acc[i][j] - mean) * rstd * gamma[col] + beta[col] + res[j];
                }
            }
        }
    }
}

// ---------------------------------------------------------------------------
// Windowed attention: one block per (b, n, window). 96 threads = (head, row).
// qkv tile (12 x 384) staged in smem. Mask only nontrivial for window 0.
// ---------------------------------------------------------------------------
__global__ __launch_bounds__(96)
void attn_kernel()
{
    __shared__ float s[12 * 384];

    int blk = blockIdx.x;
    int w   = blk % NWIN;
    int rem = blk / NWIN;
    int n   = rem % NNH;
    int b   = rem / NNH;
    size_t base = (size_t)(b * NNH + n) * LL + w * WSZ;

    int tid = threadIdx.x;
    // 12 rows * 96 float4 per row = 1152 float4, 12 each
    for (int v = tid; v < 12 * 96; v += 96) {
        int i = v / 96, c = v % 96;
        *(float4*)(&s[i * 384 + c * 4]) = *(const float4*)(g_qkv + (base + i) * 384 + c * 4);
    }
    __syncthreads();

    int h = tid / 12;
    int i = tid % 12;
    const float* q = &s[i * 384 + h * 16];
    bool gi = (i < SHIFTSZ);

    float sc[12];
    float mx = -1e30f;
    #pragma unroll
    for (int j = 0; j < 12; j++) {
        const float* kp = &s[j * 384 + 128 + h * 16];
        float a = 0.f;
        #pragma unroll
        for (int d = 0; d < 16; d++) a += q[d] * kp[d];
        a *= 0.25f;                                     // SCALE = 16^-0.5
        if (w == 0 && (gi != (j < SHIFTSZ))) a -= 100.f; // swin shift mask
        sc[j] = a;
        mx = fmaxf(mx, a);
    }
    float den = 0.f;
    #pragma unroll
    for (int j = 0; j < 12; j++) { sc[j] = expf(sc[j] - mx); den += sc[j]; }
    float inv = 1.f / den;

    float o[16];
    #pragma unroll
    for (int d = 0; d < 16; d++) o[d] = 0.f;
    #pragma unroll
    for (int j = 0; j < 12; j++) {
        float p = sc[j] * inv;
        const float* vp = &s[j * 384 + 256 + h * 16];
        #pragma unroll
        for (int d = 0; d < 16; d++) o[d] += p * vp[d];
    }

    float* dst = g_attn + (base + i) * DDIM + h * 16;
    #pragma unroll
    for (int d = 0; d < 16; d++) dst[d] = o[d];
}

// ---------------------------------------------------------------------------
extern "C" void kernel_launch(void* const* d_in, const int* in_sizes, int n_in,
                              void* d_out, int out_size)
{
    const float* x      = (const float*)d_in[0];
    const float* qkv_w  = (const float*)d_in[1];
    const float* qkv_b  = (const float*)d_in[2];
    const float* proj_w = (const float*)d_in[3];
    const float* proj_b = (const float*)d_in[4];
    const float* fc1_w  = (const float*)d_in[5];
    const float* fc1_b  = (const float*)d_in[6];
    const float* fc2_w  = (const float*)d_in[7];
    const float* fc2_b  = (const float*)d_in[8];
    const float* g1     = (const float*)d_in[9];
    const float* b1     = (const float*)d_in[10];
    const float* g2     = (const float*)d_in[11];
    const float* b2     = (const float*)d_in[12];
    float* out = (float*)d_out;

    dim3 blk(256);
    const int MB = MTOK / 128; // 1530

    // 1) QKV projection (shift+transpose gather fused into A load)
    gemm_kernel<0, 128, 384><<<dim3(MB, 3), blk>>>(qkv_w, qkv_b, nullptr, x, nullptr, nullptr);
    // 2) windowed attention
    attn_kernel<<<BB * NNH * NWIN, 96>>>();
    // 3) proj + unshift + LN1 + residual(x)
    gemm_kernel<1, 128, 128><<<dim3(MB, 1), blk>>>(proj_w, proj_b, nullptr, x, g1, b1);
    // 4) fc1 + GELU
    gemm_kernel<2, 128, 512><<<dim3(MB, 4), blk>>>(fc1_w, fc1_b, nullptr, nullptr, nullptr, nullptr);
    // 5) fc2 + LN2 + residual(x1) + scatter to (B,L,N,D)
    gemm_kernel<3, 512, 128><<<dim3(MB, 1), blk>>>(fc2_w, fc2_b, out, nullptr, g2, b2);
}